// round 2
// baseline (speedup 1.0000x reference)
#include <cuda_runtime.h>

#define NN 100000
#define EE 1600000
#define FF 64
#define KK 6
#define NBLK_SCAN 98            /* ceil(NN/1024) */
#define GB 391                  /* gemm rider blocks = ceil(NN/256) */
#define FULLMASK 0xffffffffu

// ---------------- scratch (static device globals; allocation-free) ----------
__device__ int   g_deg[NN];
__device__ float g_dinv[NN];
__device__ int   g_cnt[NN];
__device__ int   g_cursor[NN];
__device__ int   g_rowptr[NN + 1];
__device__ int   g_bsum[NBLK_SCAN];
__device__ int   g_boff[NBLK_SCAN];
__device__ int2  g_edge[EE];                  // packed (src, weight-bits)
__device__ float g_tx[5][(size_t)NN * FF];    // Tx1..Tx5

// ---------------- f32x2 GEMM core: acc[32] pairs = hrow @ sW ---------------
__device__ __forceinline__ void gemm_core(const float* __restrict__ hrow,
                                          const float* __restrict__ sW,
                                          unsigned long long* __restrict__ acc) {
#pragma unroll
    for (int j = 0; j < FF / 2; j++) acc[j] = 0ULL;
    const float4* hr = (const float4*)hrow;
#pragma unroll 4
    for (int i4 = 0; i4 < FF / 4; i4++) {
        float4 xv = hr[i4];
#pragma unroll
        for (int ii = 0; ii < 4; ii++) {
            float xs = (ii == 0) ? xv.x : (ii == 1) ? xv.y : (ii == 2) ? xv.z : xv.w;
            unsigned long long xx;
            asm("mov.b64 %0, {%1, %1};" : "=l"(xx) : "f"(xs));
            const ulonglong2* wr = (const ulonglong2*)(sW + (i4 * 4 + ii) * FF);
#pragma unroll
            for (int j = 0; j < FF / 4; j++) {
                ulonglong2 wv = wr[j];    // broadcast LDS.128 (no conflicts)
                asm("fma.rn.f32x2 %0, %1, %2, %0;" : "+l"(acc[2 * j])     : "l"(xx), "l"(wv.x));
                asm("fma.rn.f32x2 %0, %1, %2, %0;" : "+l"(acc[2 * j + 1]) : "l"(xx), "l"(wv.y));
            }
        }
    }
}

// gemm rider block body: out (+)= h @ Wk
__device__ __forceinline__ void gemm_block(const float* __restrict__ h,
                                           const float* __restrict__ Wk,
                                           float* __restrict__ out, int first) {
    __shared__ __align__(16) float sW[FF * FF];
    for (int i = threadIdx.x; i < FF * FF / 4; i += blockDim.x)
        ((float4*)sW)[i] = ((const float4*)Wk)[i];
    __syncthreads();
    int node = blockIdx.x * blockDim.x + threadIdx.x;
    if (node >= NN) return;

    unsigned long long acc[FF / 2];
    gemm_core(h + (size_t)node * FF, sW, acc);

    unsigned long long* orow = (unsigned long long*)(out + (size_t)node * FF);
    if (first) {
#pragma unroll
        for (int j = 0; j < FF / 2; j++) orow[j] = acc[j];
    } else {
#pragma unroll
        for (int j = 0; j < FF / 2; j++) {
            unsigned long long o = orow[j];
            asm("add.rn.f32x2 %0, %0, %1;" : "+l"(o) : "l"(acc[j]));
            orow[j] = o;
        }
    }
}

// ---------------- CSR build ------------------------------------------------
__global__ void zero_kernel() {
    int i = blockIdx.x * blockDim.x + threadIdx.x;
    if (i < NN) { g_deg[i] = 0; g_cnt[i] = 0; g_cursor[i] = 0; }
}

__global__ void hist_kernel(const int* __restrict__ ei) {
    int e = blockIdx.x * blockDim.x + threadIdx.x;
    if (e < EE) {
        atomicAdd(&g_deg[ei[e]], 1);        // out-degree by src
        atomicAdd(&g_cnt[ei[EE + e]], 1);   // in-degree by dst
    }
}

__global__ void dinv_kernel() {
    int i = blockIdx.x * blockDim.x + threadIdx.x;
    if (i < NN) {
        int d = g_deg[i];
        g_dinv[i] = (d > 0) ? rsqrtf((float)d) : 0.0f;
    }
}

__global__ void scanA_kernel() {
    __shared__ int sh[1024];
    int t = threadIdx.x;
    int idx = blockIdx.x * 1024 + t;
    int v = (idx < NN) ? g_cnt[idx] : 0;
    sh[t] = v;
    __syncthreads();
    for (int off = 1; off < 1024; off <<= 1) {
        int tv = (t >= off) ? sh[t - off] : 0;
        __syncthreads();
        sh[t] += tv;
        __syncthreads();
    }
    if (idx < NN) g_rowptr[idx] = sh[t] - v;
    if (t == 1023) g_bsum[blockIdx.x] = sh[1023];
}

__global__ void scanB_kernel() {
    if (threadIdx.x == 0) {
        int acc = 0;
        for (int i = 0; i < NBLK_SCAN; i++) { g_boff[i] = acc; acc += g_bsum[i]; }
        g_rowptr[NN] = acc;
    }
}

__global__ void scanC_kernel() {
    int idx = blockIdx.x * blockDim.x + threadIdx.x;
    if (idx < NN) g_rowptr[idx] += g_boff[idx >> 10];
}

// scatter + gemm0 rider (out = x @ W0, overlapped with CSR scatter)
__global__ __launch_bounds__(256) void scatter_kernel(const int* __restrict__ ei,
                                                      const float* __restrict__ x,
                                                      const float* __restrict__ W,
                                                      float* __restrict__ out) {
    if (blockIdx.x < GB) { gemm_block(x, W, out, 1); return; }
    int e = (blockIdx.x - GB) * blockDim.x + threadIdx.x;
    if (e < EE) {
        int r = ei[e];
        int c = ei[EE + e];
        int pos = g_rowptr[c] + atomicAdd(&g_cursor[c], 1);
        g_edge[pos] = make_int2(r, __float_as_int(-(g_dinv[r] * g_dinv[c])));
    }
}

// ---------------- prop + gemm rider ----------------------------------------
// prop: Tx_out = alpha * (L_hat @ h) - sub     (warp per destination node)
// rider blocks (first GB when gk>=0): out += g_h @ W[gk]
__global__ __launch_bounds__(256) void prop_kernel(const float* __restrict__ x,
                                                   const float* __restrict__ W,
                                                   float* __restrict__ out,
                                                   int h_idx, int sub_idx, float alpha,
                                                   int out_idx, int gk, int gh) {
    if (gk >= 0 && blockIdx.x < GB) {
        gemm_block(gh < 0 ? x : g_tx[gh], W + gk * FF * FF, out, 0);
        return;
    }
    int bid = (gk >= 0) ? blockIdx.x - GB : blockIdx.x;
    int gw = bid * 8 + (threadIdx.x >> 5);
    if (gw >= NN) return;
    int lane = threadIdx.x & 31;

    const float* h = (h_idx < 0) ? x : g_tx[h_idx];
    int s = g_rowptr[gw];
    int e = g_rowptr[gw + 1];

    float ax = 0.0f, ay = 0.0f;
    for (int base = s; base < e; base += 32) {
        int idx = base + lane;
        int2 ed = (idx < e) ? g_edge[idx] : make_int2(0, 0);   // one coalesced 8B lane-load
        int n = min(32, e - base);
#pragma unroll 4
        for (int j = 0; j < n; j++) {
            int   sr = __shfl_sync(FULLMASK, ed.x, j);
            float wv = __int_as_float(__shfl_sync(FULLMASK, ed.y, j));
            float2 hv = *(const float2*)(h + (size_t)sr * FF + lane * 2);  // 256B/warp gather
            ax = fmaf(wv, hv.x, ax);
            ay = fmaf(wv, hv.y, ay);
        }
    }
    float rx = alpha * ax, ry = alpha * ay;
    if (sub_idx > -2) {
        const float* sb = (sub_idx < 0) ? x : g_tx[sub_idx];
        float2 sv = *(const float2*)(sb + (size_t)gw * FF + lane * 2);
        rx -= sv.x; ry -= sv.y;
    }
    *(float2*)(g_tx[out_idx] + (size_t)gw * FF + lane * 2) = make_float2(rx, ry);
}

// ---------------- finish: out = relu(out + Tx5 @ W5 + b) --------------------
__global__ __launch_bounds__(256) void finish_kernel(const float* __restrict__ W,
                                                     const float* __restrict__ b,
                                                     float* __restrict__ out) {
    __shared__ __align__(16) float sW[FF * FF];
    __shared__ float sB[FF];
    for (int i = threadIdx.x; i < FF * FF / 4; i += blockDim.x)
        ((float4*)sW)[i] = ((const float4*)(W + 5 * FF * FF))[i];
    if (threadIdx.x < FF) sB[threadIdx.x] = b[threadIdx.x];
    __syncthreads();
    int node = blockIdx.x * blockDim.x + threadIdx.x;
    if (node >= NN) return;

    unsigned long long acc[FF / 2];
    gemm_core(g_tx[4] + (size_t)node * FF, sW, acc);

    float* orow = out + (size_t)node * FF;
#pragma unroll
    for (int j = 0; j < FF / 2; j++) {
        float2 o = ((float2*)orow)[j];
        float alo = __uint_as_float((unsigned int)(acc[j] & 0xffffffffULL));
        float ahi = __uint_as_float((unsigned int)(acc[j] >> 32));
        o.x = fmaxf(o.x + alo + sB[2 * j], 0.0f);
        o.y = fmaxf(o.y + ahi + sB[2 * j + 1], 0.0f);
        ((float2*)orow)[j] = o;
    }
}

// ---------------- launch ----------------------------------------------------
extern "C" void kernel_launch(void* const* d_in, const int* in_sizes, int n_in,
                              void* d_out, int out_size) {
    const float* x  = (const float*)d_in[0];   // [N, 64]
    const int*   ei = (const int*)d_in[1];     // [2, E]: src row then dst row
    const float* W  = (const float*)d_in[2];   // [6, 64, 64]
    const float* b  = (const float*)d_in[3];   // [64]
    float* out = (float*)d_out;                // [N, 64]

    const int TB = 256;
    const int NB_N = (NN + TB - 1) / TB;       // 391
    const int NB_E = (EE + TB - 1) / TB;       // 6250
    const int PROP_B = NN * 32 / TB;           // 12500

    zero_kernel   <<<NB_N, TB>>>();
    hist_kernel   <<<NB_E, TB>>>(ei);
    dinv_kernel   <<<NB_N, TB>>>();
    scanA_kernel  <<<NBLK_SCAN, 1024>>>();
    scanB_kernel  <<<1, 32>>>();
    scanC_kernel  <<<NB_N, TB>>>();
    scatter_kernel<<<NB_E + GB, TB>>>(ei, x, W, out);          // + gemm0 rider

    prop_kernel<<<PROP_B,      TB>>>(x, W, out, -1, -2, 1.0f, 0, -1, 0);  // Tx1
    prop_kernel<<<PROP_B + GB, TB>>>(x, W, out,  0, -1, 2.0f, 1,  1, 0);  // Tx2 + gemm1
    prop_kernel<<<PROP_B + GB, TB>>>(x, W, out,  1,  0, 2.0f, 2,  2, 1);  // Tx3 + gemm2
    prop_kernel<<<PROP_B + GB, TB>>>(x, W, out,  2,  1, 2.0f, 3,  3, 2);  // Tx4 + gemm3
    prop_kernel<<<PROP_B + GB, TB>>>(x, W, out,  3,  2, 2.0f, 4,  4, 3);  // Tx5 + gemm4

    finish_kernel<<<NB_N, TB>>>(W, b, out);                    // gemm5 + bias + relu
}

// round 4
// speedup vs baseline: 1.7277x; 1.7277x over previous
#include <cuda_runtime.h>

#define NN 100000
#define EE 1600000
#define FF 64
#define NBLK_SCAN 98            /* ceil(NN/1024) */
#define FULLMASK 0xffffffffu

// ---------------- scratch (static device globals; allocation-free) ----------
__device__ int   g_deg[NN];
__device__ float g_dinv[NN];
__device__ int   g_cnt[NN];
__device__ int   g_cursor[NN];
__device__ int   g_rowptr[NN + 1];
__device__ int   g_bsum[NBLK_SCAN];
__device__ int   g_boff[NBLK_SCAN];
__device__ int2  g_edge[EE];                  // packed (src, weight-bits)
__device__ float g_tx[5][(size_t)NN * FF];    // Tx1..Tx5

// ---------------- CSR build ------------------------------------------------
__global__ void zero_kernel() {
    int i = blockIdx.x * blockDim.x + threadIdx.x;
    if (i < NN) { g_deg[i] = 0; g_cnt[i] = 0; g_cursor[i] = 0; }
}

__global__ void hist_kernel(const int* __restrict__ ei) {
    int e = blockIdx.x * blockDim.x + threadIdx.x;
    if (e < EE) {
        atomicAdd(&g_deg[ei[e]], 1);        // out-degree by src (matches reference)
        atomicAdd(&g_cnt[ei[EE + e]], 1);   // in-degree by dst (CSR row sizes)
    }
}

__global__ void dinv_kernel() {
    int i = blockIdx.x * blockDim.x + threadIdx.x;
    if (i < NN) {
        int d = g_deg[i];
        g_dinv[i] = (d > 0) ? rsqrtf((float)d) : 0.0f;
    }
}

__global__ void scanA_kernel() {
    __shared__ int sh[1024];
    int t = threadIdx.x;
    int idx = blockIdx.x * 1024 + t;
    int v = (idx < NN) ? g_cnt[idx] : 0;
    sh[t] = v;
    __syncthreads();
    for (int off = 1; off < 1024; off <<= 1) {
        int tv = (t >= off) ? sh[t - off] : 0;
        __syncthreads();
        sh[t] += tv;
        __syncthreads();
    }
    if (idx < NN) g_rowptr[idx] = sh[t] - v;
    if (t == 1023) g_bsum[blockIdx.x] = sh[1023];
}

__global__ void scanB_kernel() {
    if (threadIdx.x == 0) {
        int acc = 0;
        for (int i = 0; i < NBLK_SCAN; i++) { g_boff[i] = acc; acc += g_bsum[i]; }
        g_rowptr[NN] = acc;
    }
}

__global__ void scanC_kernel() {
    int idx = blockIdx.x * blockDim.x + threadIdx.x;
    if (idx < NN) g_rowptr[idx] += g_boff[idx >> 10];
}

__global__ void scatter_kernel(const int* __restrict__ ei) {
    int e = blockIdx.x * blockDim.x + threadIdx.x;
    if (e < EE) {
        int r = ei[e];
        int c = ei[EE + e];
        int pos = g_rowptr[c] + atomicAdd(&g_cursor[c], 1);
        g_edge[pos] = make_int2(r, __float_as_int(-(g_dinv[r] * g_dinv[c])));
    }
}

// ---------------- rider matvec: oacc += row(smem) @ Wk(smem), lane owns 2 outs
__device__ __forceinline__ void rider_matvec(const float* __restrict__ srow,
                                             const float* __restrict__ sWk,
                                             int lane, unsigned long long& oacc) {
#pragma unroll 8
    for (int i = 0; i < FF; i++) {
        float ts = srow[i];                                  // broadcast LDS
        unsigned long long tt;
        asm("mov.b64 %0, {%1, %1};" : "=l"(tt) : "f"(ts));
        unsigned long long wb =
            *(const unsigned long long*)(sWk + i * FF + 2 * lane);  // LDS.64, conflict-free
        asm("fma.rn.f32x2 %0, %1, %2, %0;" : "+l"(oacc) : "l"(tt), "l"(wb));
    }
}

// ---------------- prop + fused gemm rider ----------------------------------
// Tx_out = alpha * (L_hat @ h) - sub   (one warp per destination node)
// then:  out (+)= Tx_out @ W[k]   (+ x @ W[0] when k==1; + bias/relu when k==5)
__global__ __launch_bounds__(256) void prop_kernel(const float* __restrict__ x,
                                                   const float* __restrict__ W,
                                                   const float* __restrict__ b,
                                                   float* __restrict__ out,
                                                   int h_idx, int sub_idx, float alpha,
                                                   int out_idx, int k) {
    __shared__ __align__(16) float sW[2 * FF * FF];   // W_k (+ W_0 for k==1)
    __shared__ float s_row[8][FF];
    __shared__ float s_x[8][FF];
    __shared__ float s_b[FF];

    // load weights for this stage into shared
    {
        const float4* src = (const float4*)(W + k * FF * FF);
        for (int i = threadIdx.x; i < FF * FF / 4; i += blockDim.x)
            ((float4*)sW)[i] = src[i];
        if (k == 1) {   // also W0
            const float4* s0 = (const float4*)W;
            for (int i = threadIdx.x; i < FF * FF / 4; i += blockDim.x)
                ((float4*)(sW + FF * FF))[i] = s0[i];
        }
        if (k == 5 && threadIdx.x < FF) s_b[threadIdx.x] = b[threadIdx.x];
    }
    __syncthreads();

    int w    = threadIdx.x >> 5;
    int lane = threadIdx.x & 31;
    int gw   = blockIdx.x * 8 + w;          // grid sized exactly: no tail
    const float* h = (h_idx < 0) ? x : g_tx[h_idx];

    int s = g_rowptr[gw];
    int e = g_rowptr[gw + 1];

    float ax = 0.0f, ay = 0.0f;
    int i = s;
    for (; i + 4 <= e; i += 4) {            // MLP=4: independent edge + gather loads
        int2 e0 = __ldg(&g_edge[i]);
        int2 e1 = __ldg(&g_edge[i + 1]);
        int2 e2 = __ldg(&g_edge[i + 2]);
        int2 e3 = __ldg(&g_edge[i + 3]);
        float2 h0 = __ldg((const float2*)(h + (size_t)e0.x * FF) + lane);
        float2 h1 = __ldg((const float2*)(h + (size_t)e1.x * FF) + lane);
        float2 h2 = __ldg((const float2*)(h + (size_t)e2.x * FF) + lane);
        float2 h3 = __ldg((const float2*)(h + (size_t)e3.x * FF) + lane);
        float w0 = __int_as_float(e0.y), w1 = __int_as_float(e1.y);
        float w2 = __int_as_float(e2.y), w3 = __int_as_float(e3.y);
        ax = fmaf(w0, h0.x, ax); ay = fmaf(w0, h0.y, ay);
        ax = fmaf(w1, h1.x, ax); ay = fmaf(w1, h1.y, ay);
        ax = fmaf(w2, h2.x, ax); ay = fmaf(w2, h2.y, ay);
        ax = fmaf(w3, h3.x, ax); ay = fmaf(w3, h3.y, ay);
    }
    for (; i < e; i++) {
        int2 ed = __ldg(&g_edge[i]);
        float2 hv = __ldg((const float2*)(h + (size_t)ed.x * FF) + lane);
        float wv = __int_as_float(ed.y);
        ax = fmaf(wv, hv.x, ax); ay = fmaf(wv, hv.y, ay);
    }

    float rx = alpha * ax, ry = alpha * ay;
    if (sub_idx > -2) {
        const float* sb = (sub_idx < 0) ? x : g_tx[sub_idx];
        float2 sv = __ldg((const float2*)(sb + (size_t)gw * FF) + lane);
        rx -= sv.x; ry -= sv.y;
    }
    // write the Chebyshev basis row
    *(float2*)(g_tx[out_idx] + (size_t)gw * FF + 2 * lane) = make_float2(rx, ry);

    // ---- rider: out (+)= Tx_k @ W_k  (lane owns output features 2l, 2l+1) ----
    s_row[w][2 * lane]     = rx;
    s_row[w][2 * lane + 1] = ry;
    if (k == 1) {
        float2 xv = __ldg((const float2*)(x + (size_t)gw * FF) + lane);
        s_x[w][2 * lane]     = xv.x;
        s_x[w][2 * lane + 1] = xv.y;
    }
    __syncwarp();

    unsigned long long oacc = 0ULL;
    rider_matvec(s_row[w], sW, lane, oacc);              // Tx_k @ W_k
    if (k == 1) rider_matvec(s_x[w], sW + FF * FF, lane, oacc);   // + x @ W_0

    float olo = __uint_as_float((unsigned int)(oacc & 0xffffffffULL));
    float ohi = __uint_as_float((unsigned int)(oacc >> 32));
    float2* orow = (float2*)(out + (size_t)gw * FF) + lane;
    float2 o;
    if (k == 1) { o.x = olo; o.y = ohi; }                 // init (out was poisoned)
    else {
        float2 prev = *orow;
        o.x = prev.x + olo; o.y = prev.y + ohi;
    }
    if (k == 5) {
        o.x = fmaxf(o.x + s_b[2 * lane], 0.0f);
        o.y = fmaxf(o.y + s_b[2 * lane + 1], 0.0f);
    }
    *orow = o;
}

// ---------------- launch ----------------------------------------------------
extern "C" void kernel_launch(void* const* d_in, const int* in_sizes, int n_in,
                              void* d_out, int out_size) {
    const float* x  = (const float*)d_in[0];   // [N, 64]
    const int*   ei = (const int*)d_in[1];     // [2, E]: src row then dst row
    const float* W  = (const float*)d_in[2];   // [6, 64, 64]
    const float* b  = (const float*)d_in[3];   // [64]
    float* out = (float*)d_out;                // [N, 64]

    const int TB = 256;
    const int NB_N = (NN + TB - 1) / TB;       // 391
    const int NB_E = (EE + TB - 1) / TB;       // 6250
    const int PROP_B = NN / 8;                 // 12500, exact (8 warps/block)

    zero_kernel   <<<NB_N, TB>>>();
    hist_kernel   <<<NB_E, TB>>>(ei);
    dinv_kernel   <<<NB_N, TB>>>();
    scanA_kernel  <<<NBLK_SCAN, 1024>>>();
    scanB_kernel  <<<1, 32>>>();
    scanC_kernel  <<<NB_N, TB>>>();
    scatter_kernel<<<NB_E, TB>>>(ei);

    //                                   h   sub  alpha  out  k
    prop_kernel<<<PROP_B, TB>>>(x, W, b, out, -1, -2, 1.0f, 0, 1);  // Tx1; out = xW0 + Tx1W1
    prop_kernel<<<PROP_B, TB>>>(x, W, b, out,  0, -1, 2.0f, 1, 2);  // Tx2; out += Tx2W2
    prop_kernel<<<PROP_B, TB>>>(x, W, b, out,  1,  0, 2.0f, 2, 3);  // Tx3; out += Tx3W3
    prop_kernel<<<PROP_B, TB>>>(x, W, b, out,  2,  1, 2.0f, 3, 4);  // Tx4; out += Tx4W4
    prop_kernel<<<PROP_B, TB>>>(x, W, b, out,  3,  2, 2.0f, 4, 5);  // Tx5; out=relu(out+Tx5W5+b)
}

// round 6
// speedup vs baseline: 2.1337x; 1.2349x over previous
#include <cuda_runtime.h>

#define NN 100000
#define EE 1600000
#define FF 64
#define KK 6
#define NBLK_SCAN 98   /* ceil(NN/1024) */

// ---------------- scratch (static device globals; allocation-free) ----------
__device__ int   g_deg[NN];
__device__ float g_dinv[NN];
__device__ int   g_cnt[NN];
__device__ int   g_cursor[NN];
__device__ int   g_rowptr[NN + 1];
__device__ int   g_bsum[NBLK_SCAN];
__device__ int   g_boff[NBLK_SCAN];
__device__ int2  g_edge[EE];                 // packed (src, weight-bits)
__device__ float g_tx[5][(size_t)NN * FF];   // Tx1..Tx5

// ---------------- CSR build ------------------------------------------------
__global__ void zero_kernel() {
    int i = blockIdx.x * blockDim.x + threadIdx.x;
    if (i < NN) { g_deg[i] = 0; g_cnt[i] = 0; g_cursor[i] = 0; }
}

__global__ void hist_kernel(const int* __restrict__ ei) {
    int e = blockIdx.x * blockDim.x + threadIdx.x;
    if (e < EE) {
        atomicAdd(&g_deg[ei[e]], 1);        // out-degree by src (row)
        atomicAdd(&g_cnt[ei[EE + e]], 1);   // in-degree by dst (col)
    }
}

__global__ void dinv_kernel() {
    int i = blockIdx.x * blockDim.x + threadIdx.x;
    if (i < NN) {
        int d = g_deg[i];
        g_dinv[i] = (d > 0) ? rsqrtf((float)d) : 0.0f;
    }
}

__global__ void scanA_kernel() {
    __shared__ int sh[1024];
    int t   = threadIdx.x;
    int idx = blockIdx.x * 1024 + t;
    int v   = (idx < NN) ? g_cnt[idx] : 0;
    sh[t] = v;
    __syncthreads();
    for (int off = 1; off < 1024; off <<= 1) {
        int tv = (t >= off) ? sh[t - off] : 0;
        __syncthreads();
        sh[t] += tv;
        __syncthreads();
    }
    if (idx < NN) g_rowptr[idx] = sh[t] - v;   // exclusive within block
    if (t == 1023) g_bsum[blockIdx.x] = sh[1023];
}

__global__ void scanB_kernel() {
    if (threadIdx.x == 0) {
        int acc = 0;
        for (int i = 0; i < NBLK_SCAN; i++) { g_boff[i] = acc; acc += g_bsum[i]; }
        g_rowptr[NN] = acc;                    // == EE
    }
}

__global__ void scanC_kernel() {
    int idx = blockIdx.x * blockDim.x + threadIdx.x;
    if (idx < NN) g_rowptr[idx] += g_boff[idx >> 10];
}

__global__ void scatter_kernel(const int* __restrict__ ei) {
    int e = blockIdx.x * blockDim.x + threadIdx.x;
    if (e < EE) {
        int r = ei[e];
        int c = ei[EE + e];
        int pos = g_rowptr[c] + atomicAdd(&g_cursor[c], 1);
        g_edge[pos] = make_int2(r, __float_as_int(-(g_dinv[r] * g_dinv[c])));
    }
}

// ---------------- propagation: out = alpha * (L_hat @ h) - sub -------------
// One warp per destination node; each lane owns 2 of the 64 features (float2).
// Identical structure to the 476us version; only the edge load is packed int2.
__global__ void prop_kernel(const float* __restrict__ x,
                            int h_idx, int sub_idx, float alpha, int out_idx) {
    int gw   = (blockIdx.x * blockDim.x + threadIdx.x) >> 5;
    int lane = threadIdx.x & 31;
    if (gw >= NN) return;

    const float* h = (h_idx < 0) ? x : g_tx[h_idx];
    int s = g_rowptr[gw];
    int e = g_rowptr[gw + 1];

    float ax = 0.0f, ay = 0.0f;
    for (int i = s; i < e; i++) {
        int2  ed = g_edge[i];                        // lane-uniform 8B broadcast (L1-hit)
        float wv = __int_as_float(ed.y);
        float2 hv = ((const float2*)(h + (size_t)ed.x * FF))[lane];  // 256B/warp gather
        ax = fmaf(wv, hv.x, ax);
        ay = fmaf(wv, hv.y, ay);
    }
    float rx = alpha * ax, ry = alpha * ay;
    if (sub_idx > -2) {
        const float* sb = (sub_idx < 0) ? x : g_tx[sub_idx];
        float2 sv = ((const float2*)(sb + (size_t)gw * FF))[lane];
        rx -= sv.x; ry -= sv.y;
    }
    float2 r; r.x = rx; r.y = ry;
    ((float2*)(g_tx[out_idx] + (size_t)gw * FF))[lane] = r;
}

// ---------------- fused GEMM: out = relu(sum_k Tx_k @ W_k + b) -------------
// One thread per node row; all 6 W matrices in dynamic shared (broadcast LDS).
// Same shape as the 476us version, but FFMA2 (fma.rn.f32x2) halves issue slots.
__global__ __launch_bounds__(256) void gemm_kernel(const float* __restrict__ x,
                                                   const float* __restrict__ W,
                                                   const float* __restrict__ b,
                                                   float* __restrict__ out) {
    extern __shared__ float sW[];   // KK*FF*FF floats = 96 KB
    for (int i = threadIdx.x; i < KK * FF * FF; i += blockDim.x) sW[i] = W[i];
    __syncthreads();

    int node = blockIdx.x * blockDim.x + threadIdx.x;
    if (node >= NN) return;

    unsigned long long acc[FF / 2];   // 32 packed f32x2 accumulators (independent)
#pragma unroll
    for (int j = 0; j < FF / 2; j++) acc[j] = 0ULL;

#pragma unroll 1
    for (int k = 0; k < KK; k++) {
        const float* hb = (k == 0) ? x : g_tx[k - 1];
        const float4* hr = (const float4*)(hb + (size_t)node * FF);
        const float*  wk = sW + k * FF * FF;
#pragma unroll 1
        for (int i4 = 0; i4 < FF / 4; i4++) {
            float4 xv = __ldg(hr + i4);
#pragma unroll
            for (int ii = 0; ii < 4; ii++) {
                float xs = (ii == 0) ? xv.x : (ii == 1) ? xv.y : (ii == 2) ? xv.z : xv.w;
                unsigned long long xx;
                asm("mov.b64 %0, {%1, %1};" : "=l"(xx) : "f"(xs));
                const ulonglong2* wr = (const ulonglong2*)(wk + (i4 * 4 + ii) * FF);
#pragma unroll
                for (int j4 = 0; j4 < FF / 4; j4++) {
                    ulonglong2 wv = wr[j4];   // broadcast LDS.128 (no bank conflict)
                    asm("fma.rn.f32x2 %0, %1, %2, %0;"
                        : "+l"(acc[2 * j4])     : "l"(xx), "l"(wv.x));
                    asm("fma.rn.f32x2 %0, %1, %2, %0;"
                        : "+l"(acc[2 * j4 + 1]) : "l"(xx), "l"(wv.y));
                }
            }
        }
    }

    float* orow = out + (size_t)node * FF;
#pragma unroll
    for (int j = 0; j < FF / 2; j++) {
        float alo = __uint_as_float((unsigned int)(acc[j] & 0xffffffffULL));
        float ahi = __uint_as_float((unsigned int)(acc[j] >> 32));
        float2 v;
        v.x = fmaxf(alo + __ldg(b + 2 * j),     0.0f);
        v.y = fmaxf(ahi + __ldg(b + 2 * j + 1), 0.0f);
        ((float2*)orow)[j] = v;
    }
}

// ---------------- launch ----------------------------------------------------
extern "C" void kernel_launch(void* const* d_in, const int* in_sizes, int n_in,
                              void* d_out, int out_size) {
    const float* x  = (const float*)d_in[0];   // [N, 64]
    const int*   ei = (const int*)d_in[1];     // [2, E] row-major: src then dst
    const float* W  = (const float*)d_in[2];   // [6, 64, 64]
    const float* b  = (const float*)d_in[3];   // [64]
    float* out = (float*)d_out;                // [N, 64]

    cudaFuncSetAttribute(gemm_kernel, cudaFuncAttributeMaxDynamicSharedMemorySize,
                         KK * FF * FF * (int)sizeof(float));

    const int TB = 256;
    zero_kernel   <<<(NN + TB - 1) / TB, TB>>>();
    hist_kernel   <<<(EE + TB - 1) / TB, TB>>>(ei);
    dinv_kernel   <<<(NN + TB - 1) / TB, TB>>>();
    scanA_kernel  <<<NBLK_SCAN, 1024>>>();
    scanB_kernel  <<<1, 32>>>();
    scanC_kernel  <<<(NN + TB - 1) / TB, TB>>>();
    scatter_kernel<<<(EE + TB - 1) / TB, TB>>>(ei);

    int prop_blocks = (NN * 32 + TB - 1) / TB;   // warp per node
    prop_kernel<<<prop_blocks, TB>>>(x, -1, -2, 1.0f, 0);  // Tx1 = L x
    prop_kernel<<<prop_blocks, TB>>>(x,  0, -1, 2.0f, 1);  // Tx2 = 2 L Tx1 - x
    prop_kernel<<<prop_blocks, TB>>>(x,  1,  0, 2.0f, 2);  // Tx3
    prop_kernel<<<prop_blocks, TB>>>(x,  2,  1, 2.0f, 3);  // Tx4
    prop_kernel<<<prop_blocks, TB>>>(x,  3,  2, 2.0f, 4);  // Tx5

    gemm_kernel<<<(NN + TB - 1) / TB, TB, KK * FF * FF * (int)sizeof(float)>>>(x, W, b, out);
}